// round 12
// baseline (speedup 1.0000x reference)
#include <cuda_runtime.h>
#include <cuda_fp16.h>
#include <math.h>
#include <cstdint>

// Problem dims (compile-time)
static constexpr int Bsz = 16384;
static constexpr int Dd  = 768;
static constexpr int Kk  = 4;
static constexpr int H1  = 512;
static constexpr int H2  = 256;
static constexpr int KD  = Kk * Dd;        // 3072

// Scratch (device globals: allocation-free per harness rules)
__device__ float  g_logits[Bsz * Dd];      // fp32 (softmax input precision)
__device__ __half g_wflath[Bsz * KD];      // fp16 wflat scratch (100 MB)
__device__ __half g_embh[Bsz * Dd];
__device__ __half g_h1h[Bsz * H1];
__device__ __half g_h2h[Bsz * H2];
__device__ __half g_W1h[Dd * H1];
__device__ __half g_W2h[H1 * H2];
__device__ __half g_Wdh[H2 * KD];
__device__ __half g_Wah[H2 * Dd];

__device__ __forceinline__ uint32_t smem_u32(const void* p) {
    uint32_t a;
    asm("{ .reg .u64 t; cvta.to.shared.u64 t, %1; cvt.u32.u64 %0, t; }"
        : "=r"(a) : "l"(p));
    return a;
}

__device__ __forceinline__ void cp_async16(uint32_t dst, const void* src) {
    asm volatile("cp.async.cg.shared.global [%0], [%1], 16;"
                 :: "r"(dst), "l"(src) : "memory");
}
#define CP_COMMIT() asm volatile("cp.async.commit_group;" ::: "memory")
#define CP_WAIT(n)  asm volatile("cp.async.wait_group %0;" :: "n"(n) : "memory")

// ===========================================================================
// FP16 mma GEMM (R9-best config): fp16 gmem -> cp.async (3-stage) -> fp16 smem
// -> ldmatrix -> m16n8k16 (fp32 accum).  C[M,N] = A[M,K] @ B[K,N] + bias[N]
// BM=128, BN=128, BK=32. 256 threads, warp tile 64x32, 2 CTAs/SM.
// OutT selects fp32 / fp16 output (bias added in fp32 either way).
// ===========================================================================
#define BM 128
#define BN 128
#define BKt 32

static constexpr int AS_STRIDE = 40;    // halves, conflict-free ldmatrix phases
static constexpr int BS_STRIDE = 136;
static constexpr int AS_ELEMS  = BM * AS_STRIDE;   // 5120 halves
static constexpr int BS_ELEMS  = BKt * BS_STRIDE;  // 4352 halves
static constexpr int NSTAGE    = 3;
static constexpr int GEMM_SMEM_BYTES = NSTAGE * (AS_ELEMS + BS_ELEMS) * 2; // 56832

template <typename OutT>
__global__ __launch_bounds__(256, 2) void mma_gemm(
    const __half* __restrict__ A, const __half* __restrict__ B,
    const float* __restrict__ bias, OutT* __restrict__ C,
    int M, int N, int Kdim)
{
    extern __shared__ __half hsm[];
    const uint32_t aBase = smem_u32(hsm);
    const uint32_t bBase = aBase + NSTAGE * AS_ELEMS * 2;

    const int tid  = threadIdx.x;
    const int lane = tid & 31;
    const int w    = tid >> 5;
    const int wm   = w >> 2;          // 0..1
    const int wn   = w & 3;           // 0..3
    const int gid  = lane >> 2;       // 0..7
    const int tig  = lane & 3;        // 0..3

    const int m0 = blockIdx.y * BM;
    const int n0 = blockIdx.x * BN;

    float acc[4][4][4];
    #pragma unroll
    for (int i = 0; i < 4; i++)
        #pragma unroll
        for (int j = 0; j < 4; j++)
            #pragma unroll
            for (int r = 0; r < 4; r++) acc[i][j][r] = 0.f;

    const int nch = Kdim / BKt;

    auto stage = [&](int kc, int s) {
        const uint32_t aB = aBase + s * AS_ELEMS * 2;
        const uint32_t bB = bBase + s * BS_ELEMS * 2;
        const int k0 = kc * BKt;
        #pragma unroll
        for (int it = 0; it < 2; it++) {
            int sid = tid + it * 256;
            int ar = sid >> 2, as = sid & 3;
            cp_async16(aB + (ar * AS_STRIDE + as * 8) * 2,
                       A + (size_t)(m0 + ar) * Kdim + k0 + as * 8);
            int br = sid >> 4, bs = sid & 15;
            cp_async16(bB + (br * BS_STRIDE + bs * 8) * 2,
                       B + (size_t)(k0 + br) * N + n0 + bs * 8);
        }
    };

    stage(0, 0); CP_COMMIT();
    stage(1, 1); CP_COMMIT();

    for (int kc = 0; kc < nch; kc++) {
        const int cur = kc % NSTAGE;
        if (kc < nch - 1) { CP_WAIT(1); } else { CP_WAIT(0); }
        __syncthreads();
        if (kc + 2 < nch) { stage(kc + 2, (kc + 2) % NSTAGE); CP_COMMIT(); }

        const uint32_t aCur = aBase + cur * AS_ELEMS * 2;
        const uint32_t bCur = bBase + cur * BS_ELEMS * 2;

        #pragma unroll
        for (int ks = 0; ks < 2; ks++) {
            const int kb = ks * 16;
            uint32_t af[4][4];
            #pragma unroll
            for (int mi = 0; mi < 4; mi++) {
                const int r = wm * 64 + mi * 16;
                uint32_t addr = aCur
                    + (uint32_t)(r + (lane & 15)) * (AS_STRIDE * 2)
                    + kb * 2 + (lane >> 4) * 16;
                asm volatile(
                    "ldmatrix.sync.aligned.m8n8.x4.shared.b16 {%0,%1,%2,%3}, [%4];"
                    : "=r"(af[mi][0]), "=r"(af[mi][1]),
                      "=r"(af[mi][2]), "=r"(af[mi][3]) : "r"(addr));
            }
            uint32_t bf[4][2];
            #pragma unroll
            for (int nj = 0; nj < 2; nj++) {
                const int c = wn * 32 + nj * 16;
                uint32_t addr = bCur
                    + (uint32_t)(kb + ((lane >> 3) & 1) * 8 + (lane & 7)) * (BS_STRIDE * 2)
                    + (uint32_t)(c + (lane >> 4) * 8) * 2;
                asm volatile(
                    "ldmatrix.sync.aligned.m8n8.x4.trans.shared.b16 {%0,%1,%2,%3}, [%4];"
                    : "=r"(bf[nj * 2][0]), "=r"(bf[nj * 2][1]),
                      "=r"(bf[nj * 2 + 1][0]), "=r"(bf[nj * 2 + 1][1]) : "r"(addr));
            }
            #pragma unroll
            for (int mi = 0; mi < 4; mi++)
                #pragma unroll
                for (int ni = 0; ni < 4; ni++) {
                    asm volatile(
                        "mma.sync.aligned.m16n8k16.row.col.f32.f16.f16.f32 "
                        "{%0,%1,%2,%3}, {%4,%5,%6,%7}, {%8,%9}, {%0,%1,%2,%3};"
                        : "+f"(acc[mi][ni][0]), "+f"(acc[mi][ni][1]),
                          "+f"(acc[mi][ni][2]), "+f"(acc[mi][ni][3])
                        : "r"(af[mi][0]), "r"(af[mi][1]), "r"(af[mi][2]), "r"(af[mi][3]),
                          "r"(bf[ni][0]), "r"(bf[ni][1]));
                }
        }
    }

    // Epilogue: + bias (fp32), store as OutT
    #pragma unroll
    for (int mi = 0; mi < 4; mi++) {
        const int r0 = m0 + wm * 64 + mi * 16 + gid;
        #pragma unroll
        for (int ni = 0; ni < 4; ni++) {
            const int c = n0 + wn * 32 + ni * 8 + tig * 2;
            const float2 bv = *(const float2*)(bias + c);
            float x0 = acc[mi][ni][0] + bv.x;
            float y0 = acc[mi][ni][1] + bv.y;
            float x1 = acc[mi][ni][2] + bv.x;
            float y1 = acc[mi][ni][3] + bv.y;
            if constexpr (sizeof(OutT) == 4) {
                *(float2*)((float*)C + (size_t)r0 * N + c)       = make_float2(x0, y0);
                *(float2*)((float*)C + (size_t)(r0 + 8) * N + c) = make_float2(x1, y1);
            } else {
                *(__half2*)((__half*)C + (size_t)r0 * N + c)       = __floats2half2_rn(x0, y0);
                *(__half2*)((__half*)C + (size_t)(r0 + 8) * N + c) = __floats2half2_rn(x1, y1);
            }
        }
    }
}

// ===========================================================================
// Converter
// ===========================================================================
__global__ void f32_to_f16_k(const float* __restrict__ s, __half* __restrict__ d,
                             int n)
{
    int i = (blockIdx.x * blockDim.x + threadIdx.x) * 4;
    if (i < n) {
        float4 v = *(const float4*)(s + i);
        __half2* p = (__half2*)(d + i);
        p[0] = __floats2half2_rn(v.x, v.y);
        p[1] = __floats2half2_rn(v.z, v.w);
    }
}

// ===========================================================================
// Block reduction (for LN)
// ===========================================================================
__device__ __forceinline__ float blockSumN(float v, float* red, int nw) {
    #pragma unroll
    for (int o = 16; o > 0; o >>= 1) v += __shfl_down_sync(0xffffffffu, v, o);
    const int lane = threadIdx.x & 31, w = threadIdx.x >> 5;
    if (lane == 0) red[w] = v;
    __syncthreads();
    if (w == 0) {
        v = (lane < nw) ? red[lane] : 0.f;
        #pragma unroll
        for (int o = 4; o > 0; o >>= 1) v += __shfl_down_sync(0xffffffffu, v, o);
        if (lane == 0) red[0] = v;
    }
    __syncthreads();
    float out = red[0];
    __syncthreads();
    return out;
}

// ===========================================================================
// One-pass LayerNorm + ReLU, in-place on fp16 (stats in fp32).
// ===========================================================================
__global__ void ln_relu_h(__half* __restrict__ x, const float* __restrict__ g,
                          const float* __restrict__ be)
{
    __shared__ float red[8];
    const int H = blockDim.x * 4;
    const int nw = blockDim.x >> 5;
    __half2* xp = (__half2*)(x + (size_t)blockIdx.x * H);
    __half2 a = xp[threadIdx.x * 2];
    __half2 b = xp[threadIdx.x * 2 + 1];
    float2 va = __half22float2(a);
    float2 vb = __half22float2(b);

    float s  = va.x + va.y + vb.x + vb.y;
    float s2 = va.x * va.x + va.y * va.y + vb.x * vb.x + vb.y * vb.y;
    s  = blockSumN(s, red, nw);
    s2 = blockSumN(s2, red, nw);
    const float mu  = s / H;
    const float var = s2 / H - mu * mu;
    const float rs  = rsqrtf(var + 1e-5f);

    float4 gg = ((const float4*)g)[threadIdx.x];
    float4 bbv = ((const float4*)be)[threadIdx.x];
    float o0 = fmaxf((va.x - mu) * rs * gg.x + bbv.x, 0.f);
    float o1 = fmaxf((va.y - mu) * rs * gg.y + bbv.y, 0.f);
    float o2 = fmaxf((vb.x - mu) * rs * gg.z + bbv.z, 0.f);
    float o3 = fmaxf((vb.y - mu) * rs * gg.w + bbv.w, 0.f);
    xp[threadIdx.x * 2]     = __floats2half2_rn(o0, o1);
    xp[threadIdx.x * 2 + 1] = __floats2half2_rn(o2, o3);
}

// ===========================================================================
// Warp-per-row epilogue: softmax(fp32 logits) -> attn; W = fp16 wflat * attn;
// Gram-Schmidt K=4; writes W_ortho [B,K,D] + attn [B,D]. No __syncthreads.
// ===========================================================================
__device__ __forceinline__ float warpSum(float v) {
    #pragma unroll
    for (int o = 16; o > 0; o >>= 1) v += __shfl_xor_sync(0xffffffffu, v, o);
    return v;
}
__device__ __forceinline__ float warpMax(float v) {
    #pragma unroll
    for (int o = 16; o > 0; o >>= 1) v = fmaxf(v, __shfl_xor_sync(0xffffffffu, v, o));
    return v;
}

__global__ void epilogue_warp(const __half* __restrict__ wflath,
                              const float* __restrict__ logits,
                              float* __restrict__ out)
{
    const int row  = blockIdx.x * 4 + (threadIdx.x >> 5);
    const int lane = threadIdx.x & 31;
    constexpr int J = Dd / 32;  // 24
    const float* lrow = logits + (size_t)row * Dd;
    const __half* wrow = wflath + (size_t)row * KD;

    // softmax over fp32 logits
    float l[J];
    float m = -INFINITY;
    #pragma unroll
    for (int j = 0; j < J; j++) {
        l[j] = lrow[lane + j * 32];
        m = fmaxf(m, l[j]);
    }
    m = warpMax(m);
    float s = 0.f;
    #pragma unroll
    for (int j = 0; j < J; j++) { l[j] = expf(l[j] - m); s += l[j]; }
    s = warpSum(s);
    const float inv_s = 1.f / s;
    float* out_attn = out + (size_t)Bsz * KD;
    #pragma unroll
    for (int j = 0; j < J; j++) {
        l[j] *= inv_s;                       // l[] now holds attn
        out_attn[(size_t)row * Dd + lane + j * 32] = l[j];
    }

    // load fp16 W rows, modulate
    float wv[Kk][J];
    #pragma unroll
    for (int k = 0; k < Kk; k++)
        #pragma unroll
        for (int j = 0; j < J; j++)
            wv[k][j] = __half2float(wrow[k * Dd + lane + j * 32]) * l[j];

    // Gram-Schmidt
    #pragma unroll
    for (int k = 0; k < Kk; k++) {
        #pragma unroll
        for (int p = 0; p < k; p++) {
            float d = 0.f;
            #pragma unroll
            for (int j = 0; j < J; j++) d += wv[k][j] * wv[p][j];
            d = warpSum(d);
            #pragma unroll
            for (int j = 0; j < J; j++) wv[k][j] -= d * wv[p][j];
        }
        float n2 = 0.f;
        #pragma unroll
        for (int j = 0; j < J; j++) n2 += wv[k][j] * wv[k][j];
        n2 = warpSum(n2);
        const float inv = 1.f / fmaxf(sqrtf(n2), 1e-12f);
        #pragma unroll
        for (int j = 0; j < J; j++) {
            wv[k][j] *= inv;
            out[(size_t)row * KD + k * Dd + lane + j * 32] = wv[k][j];
        }
    }
}

// ===========================================================================
extern "C" void kernel_launch(void* const* d_in, const int* in_sizes, int n_in,
                              void* d_out, int out_size)
{
    const float* emb = (const float*)d_in[0];
    const float* W1  = (const float*)d_in[1];
    const float* b1  = (const float*)d_in[2];
    const float* g1  = (const float*)d_in[3];
    const float* be1 = (const float*)d_in[4];
    const float* W2  = (const float*)d_in[5];
    const float* b2  = (const float*)d_in[6];
    const float* g2  = (const float*)d_in[7];
    const float* be2 = (const float*)d_in[8];
    const float* Wd  = (const float*)d_in[9];
    const float* bd  = (const float*)d_in[10];
    const float* Wa  = (const float*)d_in[11];
    const float* ba  = (const float*)d_in[12];
    float* out = (float*)d_out;

    float *logits;
    __half *wflath, *embh, *h1h, *h2h, *W1h, *W2h, *Wdh, *Wah;
    cudaGetSymbolAddress((void**)&logits, g_logits);
    cudaGetSymbolAddress((void**)&wflath, g_wflath);
    cudaGetSymbolAddress((void**)&embh, g_embh);
    cudaGetSymbolAddress((void**)&h1h, g_h1h);
    cudaGetSymbolAddress((void**)&h2h, g_h2h);
    cudaGetSymbolAddress((void**)&W1h, g_W1h);
    cudaGetSymbolAddress((void**)&W2h, g_W2h);
    cudaGetSymbolAddress((void**)&Wdh, g_Wdh);
    cudaGetSymbolAddress((void**)&Wah, g_Wah);

    cudaFuncSetAttribute(mma_gemm<float>, cudaFuncAttributeMaxDynamicSharedMemorySize,
                         GEMM_SMEM_BYTES);
    cudaFuncSetAttribute(mma_gemm<__half>, cudaFuncAttributeMaxDynamicSharedMemorySize,
                         GEMM_SMEM_BYTES);

    auto cvt = [&](const float* s, __half* d, int n) {
        f32_to_f16_k<<<(n / 4 + 255) / 256, 256>>>(s, d, n);
    };
    cvt(emb, embh, Bsz * Dd);
    cvt(W1, W1h, Dd * H1);
    cvt(W2, W2h, H1 * H2);
    cvt(Wd, Wdh, H2 * KD);
    cvt(Wa, Wah, H2 * Dd);

    // Layer 1: fp16 output directly, LN in-place on fp16
    mma_gemm<__half><<<dim3(H1 / BN, Bsz / BM), 256, GEMM_SMEM_BYTES>>>(
        embh, W1h, b1, h1h, Bsz, H1, Dd);
    ln_relu_h<<<Bsz, H1 / 4>>>(h1h, g1, be1);
    // Layer 2
    mma_gemm<__half><<<dim3(H2 / BN, Bsz / BM), 256, GEMM_SMEM_BYTES>>>(
        h1h, W2h, b2, h2h, Bsz, H2, H1);
    ln_relu_h<<<Bsz, H2 / 4>>>(h2h, g2, be2);
    // Heads: wflat (fp16 scratch) and logits (fp32)
    mma_gemm<__half><<<dim3(KD / BN, Bsz / BM), 256, GEMM_SMEM_BYTES>>>(
        h2h, Wdh, bd, wflath, Bsz, KD, H2);
    mma_gemm<float><<<dim3(Dd / BN, Bsz / BM), 256, GEMM_SMEM_BYTES>>>(
        h2h, Wah, ba, logits, Bsz, Dd, H2);
    // softmax + modulate + Gram-Schmidt (warp per row)
    epilogue_warp<<<Bsz / 4, 128>>>(wflath, logits, out);
}

// round 13
// speedup vs baseline: 1.0434x; 1.0434x over previous
#include <cuda_runtime.h>
#include <cuda_fp16.h>
#include <math.h>
#include <cstdint>

// Problem dims (compile-time)
static constexpr int Bsz = 16384;
static constexpr int Dd  = 768;
static constexpr int Kk  = 4;
static constexpr int H1  = 512;
static constexpr int H2  = 256;
static constexpr int KD  = Kk * Dd;        // 3072
static constexpr int NC  = KD + Dd;        // 3840 combined head width

// Scratch (device globals: allocation-free per harness rules)
__device__ float  g_logits[Bsz * Dd];      // fp32 (softmax input precision)
__device__ __half g_wflath[Bsz * KD];      // fp16 wflat scratch
__device__ __half g_embh[Bsz * Dd];
__device__ __half g_h1h[Bsz * H1];
__device__ __half g_h2h[Bsz * H2];
__device__ __half g_W1h[Dd * H1];
__device__ __half g_W2h[H1 * H2];
__device__ __half g_Wch[H2 * NC];          // [Wd | Wa] fp16, row stride NC

__device__ __forceinline__ uint32_t smem_u32(const void* p) {
    uint32_t a;
    asm("{ .reg .u64 t; cvta.to.shared.u64 t, %1; cvt.u32.u64 %0, t; }"
        : "=r"(a) : "l"(p));
    return a;
}

__device__ __forceinline__ void cp_async16(uint32_t dst, const void* src) {
    asm volatile("cp.async.cg.shared.global [%0], [%1], 16;"
                 :: "r"(dst), "l"(src) : "memory");
}
#define CP_COMMIT() asm volatile("cp.async.commit_group;" ::: "memory")
#define CP_WAIT(n)  asm volatile("cp.async.wait_group %0;" :: "n"(n) : "memory")

// ===========================================================================
// FP16 mma GEMM core: fp16 gmem -> cp.async (3-stage) -> fp16 smem
// -> ldmatrix -> m16n8k16 (fp32 accum).
// BM=128, BN=128, BK=32. 256 threads, warp tile 64x32, 2 CTAs/SM.
// HEADS=false: single OutT output C[M,N]+bias.
// HEADS=true : mixed store — block cols < KD go fp16 to wflath (stride KD),
//              cols >= KD go fp32 to logits (stride Dd); bias from bd/ba.
// ===========================================================================
#define BM 128
#define BN 128
#define BKt 32

static constexpr int AS_STRIDE = 40;    // halves, conflict-free ldmatrix phases
static constexpr int BS_STRIDE = 136;
static constexpr int AS_ELEMS  = BM * AS_STRIDE;   // 5120 halves
static constexpr int BS_ELEMS  = BKt * BS_STRIDE;  // 4352 halves
static constexpr int NSTAGE    = 3;
static constexpr int GEMM_SMEM_BYTES = NSTAGE * (AS_ELEMS + BS_ELEMS) * 2; // 56832

template <bool HEADS, typename OutT>
__global__ __launch_bounds__(256, 2) void mma_gemm(
    const __half* __restrict__ A, const __half* __restrict__ B,
    const float* __restrict__ bias, OutT* __restrict__ C,
    const float* __restrict__ bias2,          // HEADS: ba
    __half* __restrict__ Cw,                  // HEADS: wflath
    float* __restrict__ Cl,                   // HEADS: logits
    int M, int N, int Kdim)
{
    extern __shared__ __half hsm[];
    const uint32_t aBase = smem_u32(hsm);
    const uint32_t bBase = aBase + NSTAGE * AS_ELEMS * 2;

    const int tid  = threadIdx.x;
    const int lane = tid & 31;
    const int w    = tid >> 5;
    const int wm   = w >> 2;          // 0..1
    const int wn   = w & 3;           // 0..3
    const int gid  = lane >> 2;       // 0..7
    const int tig  = lane & 3;        // 0..3

    const int m0 = blockIdx.y * BM;
    const int n0 = blockIdx.x * BN;

    float acc[4][4][4];
    #pragma unroll
    for (int i = 0; i < 4; i++)
        #pragma unroll
        for (int j = 0; j < 4; j++)
            #pragma unroll
            for (int r = 0; r < 4; r++) acc[i][j][r] = 0.f;

    const int nch = Kdim / BKt;

    auto stage = [&](int kc, int s) {
        const uint32_t aB = aBase + s * AS_ELEMS * 2;
        const uint32_t bB = bBase + s * BS_ELEMS * 2;
        const int k0 = kc * BKt;
        #pragma unroll
        for (int it = 0; it < 2; it++) {
            int sid = tid + it * 256;
            int ar = sid >> 2, as = sid & 3;
            cp_async16(aB + (ar * AS_STRIDE + as * 8) * 2,
                       A + (size_t)(m0 + ar) * Kdim + k0 + as * 8);
            int br = sid >> 4, bs = sid & 15;
            cp_async16(bB + (br * BS_STRIDE + bs * 8) * 2,
                       B + (size_t)(k0 + br) * N + n0 + bs * 8);
        }
    };

    stage(0, 0); CP_COMMIT();
    stage(1, 1); CP_COMMIT();

    for (int kc = 0; kc < nch; kc++) {
        const int cur = kc % NSTAGE;
        if (kc < nch - 1) { CP_WAIT(1); } else { CP_WAIT(0); }
        __syncthreads();
        if (kc + 2 < nch) { stage(kc + 2, (kc + 2) % NSTAGE); CP_COMMIT(); }

        const uint32_t aCur = aBase + cur * AS_ELEMS * 2;
        const uint32_t bCur = bBase + cur * BS_ELEMS * 2;

        #pragma unroll
        for (int ks = 0; ks < 2; ks++) {
            const int kb = ks * 16;
            uint32_t af[4][4];
            #pragma unroll
            for (int mi = 0; mi < 4; mi++) {
                const int r = wm * 64 + mi * 16;
                uint32_t addr = aCur
                    + (uint32_t)(r + (lane & 15)) * (AS_STRIDE * 2)
                    + kb * 2 + (lane >> 4) * 16;
                asm volatile(
                    "ldmatrix.sync.aligned.m8n8.x4.shared.b16 {%0,%1,%2,%3}, [%4];"
                    : "=r"(af[mi][0]), "=r"(af[mi][1]),
                      "=r"(af[mi][2]), "=r"(af[mi][3]) : "r"(addr));
            }
            uint32_t bf[4][2];
            #pragma unroll
            for (int nj = 0; nj < 2; nj++) {
                const int c = wn * 32 + nj * 16;
                uint32_t addr = bCur
                    + (uint32_t)(kb + ((lane >> 3) & 1) * 8 + (lane & 7)) * (BS_STRIDE * 2)
                    + (uint32_t)(c + (lane >> 4) * 8) * 2;
                asm volatile(
                    "ldmatrix.sync.aligned.m8n8.x4.trans.shared.b16 {%0,%1,%2,%3}, [%4];"
                    : "=r"(bf[nj * 2][0]), "=r"(bf[nj * 2][1]),
                      "=r"(bf[nj * 2 + 1][0]), "=r"(bf[nj * 2 + 1][1]) : "r"(addr));
            }
            #pragma unroll
            for (int mi = 0; mi < 4; mi++)
                #pragma unroll
                for (int ni = 0; ni < 4; ni++) {
                    asm volatile(
                        "mma.sync.aligned.m16n8k16.row.col.f32.f16.f16.f32 "
                        "{%0,%1,%2,%3}, {%4,%5,%6,%7}, {%8,%9}, {%0,%1,%2,%3};"
                        : "+f"(acc[mi][ni][0]), "+f"(acc[mi][ni][1]),
                          "+f"(acc[mi][ni][2]), "+f"(acc[mi][ni][3])
                        : "r"(af[mi][0]), "r"(af[mi][1]), "r"(af[mi][2]), "r"(af[mi][3]),
                          "r"(bf[ni][0]), "r"(bf[ni][1]));
                }
        }
    }

    // Epilogue
    if constexpr (HEADS) {
        const bool isW = (n0 < KD);   // whole block is one region (KD % BN == 0)
        #pragma unroll
        for (int mi = 0; mi < 4; mi++) {
            const int r0 = m0 + wm * 64 + mi * 16 + gid;
            #pragma unroll
            for (int ni = 0; ni < 4; ni++) {
                const int c = n0 + wn * 32 + ni * 8 + tig * 2;
                if (isW) {
                    const float2 bv = *(const float2*)(bias + c);
                    *(__half2*)(Cw + (size_t)r0 * KD + c) =
                        __floats2half2_rn(acc[mi][ni][0] + bv.x, acc[mi][ni][1] + bv.y);
                    *(__half2*)(Cw + (size_t)(r0 + 8) * KD + c) =
                        __floats2half2_rn(acc[mi][ni][2] + bv.x, acc[mi][ni][3] + bv.y);
                } else {
                    const int cl = c - KD;
                    const float2 bv = *(const float2*)(bias2 + cl);
                    *(float2*)(Cl + (size_t)r0 * Dd + cl) =
                        make_float2(acc[mi][ni][0] + bv.x, acc[mi][ni][1] + bv.y);
                    *(float2*)(Cl + (size_t)(r0 + 8) * Dd + cl) =
                        make_float2(acc[mi][ni][2] + bv.x, acc[mi][ni][3] + bv.y);
                }
            }
        }
    } else {
        #pragma unroll
        for (int mi = 0; mi < 4; mi++) {
            const int r0 = m0 + wm * 64 + mi * 16 + gid;
            #pragma unroll
            for (int ni = 0; ni < 4; ni++) {
                const int c = n0 + wn * 32 + ni * 8 + tig * 2;
                const float2 bv = *(const float2*)(bias + c);
                float x0 = acc[mi][ni][0] + bv.x;
                float y0 = acc[mi][ni][1] + bv.y;
                float x1 = acc[mi][ni][2] + bv.x;
                float y1 = acc[mi][ni][3] + bv.y;
                *(__half2*)((__half*)C + (size_t)r0 * N + c)       = __floats2half2_rn(x0, y0);
                *(__half2*)((__half*)C + (size_t)(r0 + 8) * N + c) = __floats2half2_rn(x1, y1);
            }
        }
    }
}

// ===========================================================================
// Converters: one 3-segment contiguous kernel + strided for Wch
// ===========================================================================
__global__ void cvt3_k(const float* __restrict__ s0, __half* __restrict__ d0, int n0,
                       const float* __restrict__ s1, __half* __restrict__ d1, int n1,
                       const float* __restrict__ s2, __half* __restrict__ d2, int n2)
{
    int q = blockIdx.x * blockDim.x + threadIdx.x;   // quad index
    int i = q * 4;
    const float* s; __half* d; int off;
    if (i < n0)           { s = s0; d = d0; off = i; }
    else if (i < n0 + n1) { s = s1; d = d1; off = i - n0; }
    else if (i < n0 + n1 + n2) { s = s2; d = d2; off = i - n0 - n1; }
    else return;
    float4 v = *(const float4*)(s + off);
    __half2* p = (__half2*)(d + off);
    p[0] = __floats2half2_rn(v.x, v.y);
    p[1] = __floats2half2_rn(v.z, v.w);
}

__global__ void f32_to_f16_strided(const float* __restrict__ s, __half* __restrict__ d,
                                   int srcCols, int dstStride, int colOff, int n)
{
    int i = (blockIdx.x * blockDim.x + threadIdx.x) * 4;
    if (i < n) {
        int r = i / srcCols, c = i % srcCols;   // srcCols % 4 == 0
        float4 v = *(const float4*)(s + i);
        __half2* p = (__half2*)(d + (size_t)r * dstStride + colOff + c);
        p[0] = __floats2half2_rn(v.x, v.y);
        p[1] = __floats2half2_rn(v.z, v.w);
    }
}

// ===========================================================================
// Block reduction (for LN)
// ===========================================================================
__device__ __forceinline__ float blockSumN(float v, float* red, int nw) {
    #pragma unroll
    for (int o = 16; o > 0; o >>= 1) v += __shfl_down_sync(0xffffffffu, v, o);
    const int lane = threadIdx.x & 31, w = threadIdx.x >> 5;
    if (lane == 0) red[w] = v;
    __syncthreads();
    if (w == 0) {
        v = (lane < nw) ? red[lane] : 0.f;
        #pragma unroll
        for (int o = 4; o > 0; o >>= 1) v += __shfl_down_sync(0xffffffffu, v, o);
        if (lane == 0) red[0] = v;
    }
    __syncthreads();
    float out = red[0];
    __syncthreads();
    return out;
}

// ===========================================================================
// One-pass LayerNorm + ReLU, in-place on fp16 (stats in fp32).
// ===========================================================================
__global__ void ln_relu_h(__half* __restrict__ x, const float* __restrict__ g,
                          const float* __restrict__ be)
{
    __shared__ float red[8];
    const int H = blockDim.x * 4;
    const int nw = blockDim.x >> 5;
    __half2* xp = (__half2*)(x + (size_t)blockIdx.x * H);
    __half2 a = xp[threadIdx.x * 2];
    __half2 b = xp[threadIdx.x * 2 + 1];
    float2 va = __half22float2(a);
    float2 vb = __half22float2(b);

    float s  = va.x + va.y + vb.x + vb.y;
    float s2 = va.x * va.x + va.y * va.y + vb.x * vb.x + vb.y * vb.y;
    s  = blockSumN(s, red, nw);
    s2 = blockSumN(s2, red, nw);
    const float mu  = s / H;
    const float var = s2 / H - mu * mu;
    const float rs  = rsqrtf(var + 1e-5f);

    float4 gg = ((const float4*)g)[threadIdx.x];
    float4 bbv = ((const float4*)be)[threadIdx.x];
    float o0 = fmaxf((va.x - mu) * rs * gg.x + bbv.x, 0.f);
    float o1 = fmaxf((va.y - mu) * rs * gg.y + bbv.y, 0.f);
    float o2 = fmaxf((vb.x - mu) * rs * gg.z + bbv.z, 0.f);
    float o3 = fmaxf((vb.y - mu) * rs * gg.w + bbv.w, 0.f);
    xp[threadIdx.x * 2]     = __floats2half2_rn(o0, o1);
    xp[threadIdx.x * 2 + 1] = __floats2half2_rn(o2, o3);
}

// ===========================================================================
// Warp-per-row epilogue: softmax(fp32 logits) -> attn; W = fp16 wflat * attn;
// Gram-Schmidt K=4; writes W_ortho [B,K,D] + attn [B,D]. No __syncthreads.
// ===========================================================================
__device__ __forceinline__ float warpSum(float v) {
    #pragma unroll
    for (int o = 16; o > 0; o >>= 1) v += __shfl_xor_sync(0xffffffffu, v, o);
    return v;
}
__device__ __forceinline__ float warpMax(float v) {
    #pragma unroll
    for (int o = 16; o > 0; o >>= 1) v = fmaxf(v, __shfl_xor_sync(0xffffffffu, v, o));
    return v;
}

__global__ void epilogue_warp(const __half* __restrict__ wflath,
                              const float* __restrict__ logits,
                              float* __restrict__ out)
{
    const int row  = blockIdx.x * 4 + (threadIdx.x >> 5);
    const int lane = threadIdx.x & 31;
    constexpr int J = Dd / 32;  // 24
    const float* lrow = logits + (size_t)row * Dd;
    const __half* wrow = wflath + (size_t)row * KD;

    // softmax over fp32 logits
    float l[J];
    float m = -INFINITY;
    #pragma unroll
    for (int j = 0; j < J; j++) {
        l[j] = lrow[lane + j * 32];
        m = fmaxf(m, l[j]);
    }
    m = warpMax(m);
    float s = 0.f;
    #pragma unroll
    for (int j = 0; j < J; j++) { l[j] = expf(l[j] - m); s += l[j]; }
    s = warpSum(s);
    const float inv_s = 1.f / s;
    float* out_attn = out + (size_t)Bsz * KD;
    #pragma unroll
    for (int j = 0; j < J; j++) {
        l[j] *= inv_s;                       // l[] now holds attn
        out_attn[(size_t)row * Dd + lane + j * 32] = l[j];
    }

    // load fp16 W rows, modulate
    float wv[Kk][J];
    #pragma unroll
    for (int k = 0; k < Kk; k++)
        #pragma unroll
        for (int j = 0; j < J; j++)
            wv[k][j] = __half2float(wrow[k * Dd + lane + j * 32]) * l[j];

    // Gram-Schmidt
    #pragma unroll
    for (int k = 0; k < Kk; k++) {
        #pragma unroll
        for (int p = 0; p < k; p++) {
            float d = 0.f;
            #pragma unroll
            for (int j = 0; j < J; j++) d += wv[k][j] * wv[p][j];
            d = warpSum(d);
            #pragma unroll
            for (int j = 0; j < J; j++) wv[k][j] -= d * wv[p][j];
        }
        float n2 = 0.f;
        #pragma unroll
        for (int j = 0; j < J; j++) n2 += wv[k][j] * wv[k][j];
        n2 = warpSum(n2);
        const float inv = 1.f / fmaxf(sqrtf(n2), 1e-12f);
        #pragma unroll
        for (int j = 0; j < J; j++) {
            wv[k][j] *= inv;
            out[(size_t)row * KD + k * Dd + lane + j * 32] = wv[k][j];
        }
    }
}

// ===========================================================================
extern "C" void kernel_launch(void* const* d_in, const int* in_sizes, int n_in,
                              void* d_out, int out_size)
{
    const float* emb = (const float*)d_in[0];
    const float* W1  = (const float*)d_in[1];
    const float* b1  = (const float*)d_in[2];
    const float* g1  = (const float*)d_in[3];
    const float* be1 = (const float*)d_in[4];
    const float* W2  = (const float*)d_in[5];
    const float* b2  = (const float*)d_in[6];
    const float* g2  = (const float*)d_in[7];
    const float* be2 = (const float*)d_in[8];
    const float* Wd  = (const float*)d_in[9];
    const float* bd  = (const float*)d_in[10];
    const float* Wa  = (const float*)d_in[11];
    const float* ba  = (const float*)d_in[12];
    float* out = (float*)d_out;

    float *logits;
    __half *wflath, *embh, *h1h, *h2h, *W1h, *W2h, *Wch;
    cudaGetSymbolAddress((void**)&logits, g_logits);
    cudaGetSymbolAddress((void**)&wflath, g_wflath);
    cudaGetSymbolAddress((void**)&embh, g_embh);
    cudaGetSymbolAddress((void**)&h1h, g_h1h);
    cudaGetSymbolAddress((void**)&h2h, g_h2h);
    cudaGetSymbolAddress((void**)&W1h, g_W1h);
    cudaGetSymbolAddress((void**)&W2h, g_W2h);
    cudaGetSymbolAddress((void**)&Wch, g_Wch);

    cudaFuncSetAttribute((const void*)mma_gemm<false, __half>,
                         cudaFuncAttributeMaxDynamicSharedMemorySize, GEMM_SMEM_BYTES);
    cudaFuncSetAttribute((const void*)mma_gemm<true, __half>,
                         cudaFuncAttributeMaxDynamicSharedMemorySize, GEMM_SMEM_BYTES);

    // Converts: emb + W1 + W2 in one kernel; Wd/Wa into combined Wch
    {
        int n0 = Bsz * Dd, n1 = Dd * H1, n2 = H1 * H2;
        int q = (n0 + n1 + n2) / 4;
        cvt3_k<<<(q + 255) / 256, 256>>>(emb, embh, n0, W1, W1h, n1, W2, W2h, n2);
    }
    f32_to_f16_strided<<<(H2 * KD / 4 + 255) / 256, 256>>>(Wd, Wch, KD, NC, 0,  H2 * KD);
    f32_to_f16_strided<<<(H2 * Dd / 4 + 255) / 256, 256>>>(Wa, Wch, Dd, NC, KD, H2 * Dd);

    // Layer 1: fp16 output directly, LN in-place on fp16
    mma_gemm<false, __half><<<dim3(H1 / BN, Bsz / BM), 256, GEMM_SMEM_BYTES>>>(
        embh, W1h, b1, h1h, nullptr, nullptr, nullptr, Bsz, H1, Dd);
    ln_relu_h<<<Bsz, H1 / 4>>>(h1h, g1, be1);
    // Layer 2
    mma_gemm<false, __half><<<dim3(H2 / BN, Bsz / BM), 256, GEMM_SMEM_BYTES>>>(
        h1h, W2h, b2, h2h, nullptr, nullptr, nullptr, Bsz, H2, H1);
    ln_relu_h<<<Bsz, H2 / 4>>>(h2h, g2, be2);
    // Merged heads with mixed store: wflat -> fp16, logits -> fp32
    mma_gemm<true, __half><<<dim3(NC / BN, Bsz / BM), 256, GEMM_SMEM_BYTES>>>(
        h2h, Wch, bd, nullptr, ba, wflath, logits, Bsz, NC, H2);
    // softmax + modulate + Gram-Schmidt (warp per row)
    epilogue_warp<<<Bsz / 4, 128>>>(wflath, logits, out);
}